// round 6
// baseline (speedup 1.0000x reference)
#include <cuda_runtime.h>

// Shapes (fixed by problem)
#define BB 4
#define LL 2048
#define DD 1024
#define HH 64

#define NQT 32          // q tiles per batch (L/64)
#define CHUNK 8         // key tiles per split-KV chunk
#define MAXCH 4         // max chunks per q tile
#define NBLK 80         // chunk-blocks per batch: 8*1 + 8*2 + 8*3 + 8*4

// Scratch (device globals -- no allocation allowed)
__device__ float g_q[BB * LL * HH];                         // 2 MB
__device__ float g_po[BB * NQT * MAXCH][64][HH];            // 8 MB partial O (unnormalized)
__device__ float g_pm[BB * NQT * MAXCH][64];                // partial row max
__device__ float g_pl[BB * NQT * MAXCH][64];                // partial row sum

// ---------------- packed fp32x2 helpers (FFMA2 path, sm_103a) ----------------
typedef unsigned long long u64;

__device__ __forceinline__ void ffma2(u64& d, u64 a, u64 b) {
    asm("fma.rn.f32x2 %0, %1, %2, %0;" : "+l"(d) : "l"(a), "l"(b));
}
__device__ __forceinline__ void mul2(u64& d, u64 a, u64 b) {
    asm("mul.rn.f32x2 %0, %1, %2;" : "=l"(d) : "l"(a), "l"(b));
}
__device__ __forceinline__ u64 pack2(float lo, float hi) {
    u64 r;
    asm("mov.b64 %0, {%1, %2};" : "=l"(r) : "f"(lo), "f"(hi));
    return r;
}
__device__ __forceinline__ float2 unpack2(u64 v) {
    float2 r;
    asm("mov.b64 {%0, %1}, %2;" : "=f"(r.x), "=f"(r.y) : "l"(v));
    return r;
}
__device__ __forceinline__ float hsum2(u64 v) {
    float2 u = unpack2(v);
    return u.x + u.y;
}

// ----------------------------------------------------------------------------
// Kernel 1: q = x @ Wq^T    (M=8192, N=64, K=1024), dot2 FFMA2 core.
// xs plain row-major (a-side, broadcast reads); Wq packed as swizzled u64
// k-pairs (b-side, conflict-free 16-lane reads). K-tile = 64.
// ----------------------------------------------------------------------------
__global__ __launch_bounds__(256) void proj_kernel(const float* __restrict__ x,
                                                   const float* __restrict__ Wq) {
    __shared__ float xs[64][64];      // [m][k] plain, 16 KB
    __shared__ u64   smW[64 * 32];    // [n][kpair ^ swz(n)], 16 KB

    const int t  = threadIdx.x;
    const int tr = t >> 4;            // 0..15
    const int tc = t & 15;            // 0..15
    const int m0 = blockIdx.x * 64;
    const int r0 = tr * 4;
    const int c0 = tc * 4;

    u64 acc2[4][4];                   // lanes = (even-k partial, odd-k partial)
#pragma unroll
    for (int i = 0; i < 4; i++)
#pragma unroll
        for (int j = 0; j < 4; j++) acc2[i][j] = 0ULL;

    for (int k0 = 0; k0 < DD; k0 += 64) {
#pragma unroll
        for (int i = 0; i < 4; i++) {
            int li4 = t + i * 256;          // 0..1023
            int r  = li4 >> 4;              // 0..63
            int c4 = (li4 & 15) * 4;        // 0..60
            // x tile: plain float4 store
            float4 vx = *reinterpret_cast<const float4*>(&x[(size_t)(m0 + r) * DD + k0 + c4]);
            *reinterpret_cast<float4*>(&xs[r][c4]) = vx;
            // Wq tile: pack k-pairs, swizzled u64 store
            float4 vw = *reinterpret_cast<const float4*>(&Wq[(size_t)r * DD + k0 + c4]);
            int sw = (r >> 2) & 15;
            smW[r * 32 + (((c4 >> 1) + 0) ^ sw)] = pack2(vw.x, vw.y);
            smW[r * 32 + (((c4 >> 1) + 1) ^ sw)] = pack2(vw.z, vw.w);
        }
        __syncthreads();

#pragma unroll 8
        for (int tt = 0; tt < 32; tt++) {
            u64 a2[4], b2[4];
#pragma unroll
            for (int i = 0; i < 4; i++)
                a2[i] = *reinterpret_cast<const u64*>(&xs[r0 + i][2 * tt]);
#pragma unroll
            for (int j = 0; j < 4; j++)
                b2[j] = smW[(c0 + j) * 32 + (tt ^ tc)];
#pragma unroll
            for (int i = 0; i < 4; i++)
#pragma unroll
                for (int j = 0; j < 4; j++) ffma2(acc2[i][j], a2[i], b2[j]);
        }
        __syncthreads();
    }

#pragma unroll
    for (int i = 0; i < 4; i++) {
        float4 v = make_float4(hsum2(acc2[i][0]), hsum2(acc2[i][1]),
                               hsum2(acc2[i][2]), hsum2(acc2[i][3]));
        *reinterpret_cast<float4*>(&g_q[(size_t)(m0 + r0 + i) * HH + c0]) = v;
    }
}

// ----------------------------------------------------------------------------
// Kernel 2: split-KV causal flash attention, dot2 FFMA2 core, reg-prefetched
// K-tile pipeline. Smem (48 KB exactly):
//   qs  [64][64] plain         -- Q, a-side of S (broadcast reads)
//   smA [64*32] u64            -- K d-pairs swizzled (b-side of S); ALIASED by
//                                 P kk-pairs after S phase (sync-separated)
//   smB [64*32] u64 (floats)   -- K transposed [d][key] swizzled (b-side of PV)
// ----------------------------------------------------------------------------
__global__ __launch_bounds__(256, 2) void attn_split_kernel() {
    __shared__ float qs[64][64];
    __shared__ u64   smA[64 * 32];
    __shared__ u64   smB[64 * 32];

    float* Bf = reinterpret_cast<float*>(smB);

    const int t  = threadIdx.x;
    const int tr = t >> 4;
    const int tc = t & 15;
    const int b  = blockIdx.y;
    const int r0 = tr * 4;
    const int c0 = tc * 4;

    // map flat chunk id -> (qb, ci)
    int id = blockIdx.x;              // 0..79
    int qb, ci;
    if (id < 8)       { qb = id;                 ci = 0; }
    else if (id < 24) { int e = id - 8;  qb = 8  + (e >> 1); ci = e & 1; }
    else if (id < 48) { int e = id - 24; qb = 16 + e / 3;    ci = e % 3; }
    else              { int e = id - 48; qb = 24 + (e >> 2); ci = e & 3; }

    const int jstart = ci * CHUNK;
    const int jend   = min(jstart + CHUNK, qb + 1);   // exclusive

    const float* qbase = g_q + (size_t)b * LL * HH;

    // Load q tile [64 x 64] plain
#pragma unroll
    for (int i = 0; i < 4; i++) {
        int li4 = t + i * 256;
        int r  = li4 >> 4;
        int c4 = (li4 & 15) * 4;
        float4 v = *reinterpret_cast<const float4*>(&qbase[(size_t)(qb * 64 + r) * HH + c4]);
        *reinterpret_cast<float4*>(&qs[r][c4]) = v;
    }

    // Prefetch first K tile into registers (gmem -> regs, no smem involved)
    float4 pf[4];
#pragma unroll
    for (int i = 0; i < 4; i++) {
        int li4 = t + i * 256;
        int r  = li4 >> 4;
        int c4 = (li4 & 15) * 4;
        pf[i] = *reinterpret_cast<const float4*>(&qbase[(size_t)(jstart * 64 + r) * HH + c4]);
    }

    float m[4], l[4];
    u64 o2[4][4];                     // lanes = (even-kk partial, odd-kk partial)
#pragma unroll
    for (int i = 0; i < 4; i++) { m[i] = -1e30f; l[i] = 0.f; }
#pragma unroll
    for (int i = 0; i < 4; i++)
#pragma unroll
        for (int j = 0; j < 4; j++) o2[i][j] = 0ULL;

    for (int j0 = jstart; j0 < jend; j0++) {
        __syncthreads();   // prior PV reads of smA/smB done; qs writes visible
        // Store prefetched k tile: A = [key][d-pair ^ swz] u64;
        //                          B = transpose [d][key ^ 2*swz] floats
#pragma unroll
        for (int i = 0; i < 4; i++) {
            int li4 = t + i * 256;
            int r  = li4 >> 4;              // key
            int c4 = (li4 & 15) * 4;        // d
            float4 v = pf[i];
            int swA = (r >> 2) & 15;
            smA[r * 32 + (((c4 >> 1) + 0) ^ swA)] = pack2(v.x, v.y);
            smA[r * 32 + (((c4 >> 1) + 1) ^ swA)] = pack2(v.z, v.w);
            Bf[(c4 + 0) * 64 + (r ^ ((((c4 + 0) >> 2) & 15) << 1))] = v.x;
            Bf[(c4 + 1) * 64 + (r ^ ((((c4 + 1) >> 2) & 15) << 1))] = v.y;
            Bf[(c4 + 2) * 64 + (r ^ ((((c4 + 2) >> 2) & 15) << 1))] = v.z;
            Bf[(c4 + 3) * 64 + (r ^ ((((c4 + 3) >> 2) & 15) << 1))] = v.w;
        }
        // Issue prefetch for NEXT tile now; LDG latency overlaps S+softmax+PV
        if (j0 + 1 < jend) {
#pragma unroll
            for (int i = 0; i < 4; i++) {
                int li4 = t + i * 256;
                int r  = li4 >> 4;
                int c4 = (li4 & 15) * 4;
                pf[i] = *reinterpret_cast<const float4*>(
                    &qbase[(size_t)((j0 + 1) * 64 + r) * HH + c4]);
            }
        }
        __syncthreads();

        // ---- S = (Q K^T) / 32, dot2 over d ----
        u64 s2[4][4];
#pragma unroll
        for (int i = 0; i < 4; i++)
#pragma unroll
            for (int j = 0; j < 4; j++) s2[i][j] = 0ULL;

#pragma unroll 8
        for (int tt = 0; tt < 32; tt++) {
            u64 a2[4], b2[4];
#pragma unroll
            for (int i = 0; i < 4; i++)
                a2[i] = *reinterpret_cast<const u64*>(&qs[r0 + i][2 * tt]);
#pragma unroll
            for (int j = 0; j < 4; j++)
                b2[j] = smA[(c0 + j) * 32 + (tt ^ tc)];
#pragma unroll
            for (int i = 0; i < 4; i++)
#pragma unroll
                for (int j = 0; j < 4; j++) ffma2(s2[i][j], a2[i], b2[j]);
        }

        float s[4][4];
#pragma unroll
        for (int i = 0; i < 4; i++)
#pragma unroll
            for (int j = 0; j < 4; j++)
                s[i][j] = hsum2(s2[i][j]) * 0.03125f;   // 1/sqrt(1024)

        if (j0 == qb) {
#pragma unroll
            for (int i = 0; i < 4; i++)
#pragma unroll
                for (int j = 0; j < 4; j++)
                    if (c0 + j > r0 + i) s[i][j] = -1e30f;
        }

        // ---- online softmax (row reduced across 16 tc lanes) ----
        float alpha[4];
#pragma unroll
        for (int i = 0; i < 4; i++) {
            float mx = fmaxf(fmaxf(s[i][0], s[i][1]), fmaxf(s[i][2], s[i][3]));
#pragma unroll
            for (int off = 8; off >= 1; off >>= 1)
                mx = fmaxf(mx, __shfl_xor_sync(0xffffffffu, mx, off));
            float mn = fmaxf(m[i], mx);
            alpha[i] = __expf(m[i] - mn);
            m[i] = mn;
            float rs = 0.f;
#pragma unroll
            for (int j = 0; j < 4; j++) {
                s[i][j] = __expf(s[i][j] - mn);
                rs += s[i][j];
            }
#pragma unroll
            for (int off = 8; off >= 1; off >>= 1)
                rs += __shfl_xor_sync(0xffffffffu, rs, off);
            l[i] = l[i] * alpha[i] + rs;
        }
        // rescale packed O accumulators (both lanes are partials of same output)
#pragma unroll
        for (int i = 0; i < 4; i++) {
            u64 ap = pack2(alpha[i], alpha[i]);
#pragma unroll
            for (int j = 0; j < 4; j++) mul2(o2[i][j], o2[i][j], ap);
        }

        __syncthreads();   // all S reads of smA done before aliasing with P
        // ---- write P as kk-pairs into smA (alias) ----
#pragma unroll
        for (int i = 0; i < 4; i++) {
            smA[(r0 + i) * 32 + 2 * tc + 0] = pack2(s[i][0], s[i][1]);
            smA[(r0 + i) * 32 + 2 * tc + 1] = pack2(s[i][2], s[i][3]);
        }
        __syncthreads();

        // ---- O += P @ V (V = K tile), dot2 over kk ----
#pragma unroll 8
        for (int tt = 0; tt < 32; tt++) {
            u64 a2[4], b2[4];
#pragma unroll
            for (int i = 0; i < 4; i++)
                a2[i] = smA[(r0 + i) * 32 + tt];
#pragma unroll
            for (int j = 0; j < 4; j++)
                b2[j] = smB[(c0 + j) * 32 + (tt ^ tc)];
#pragma unroll
            for (int i = 0; i < 4; i++)
#pragma unroll
                for (int j = 0; j < 4; j++) ffma2(o2[i][j], a2[i], b2[j]);
        }
    }

    // Epilogue: reduce pairs, store unnormalized partials + (m, l)
    const int slot = ((b * NQT) + qb) * MAXCH + ci;
#pragma unroll
    for (int i = 0; i < 4; i++) {
        float4 v = make_float4(hsum2(o2[i][0]), hsum2(o2[i][1]),
                               hsum2(o2[i][2]), hsum2(o2[i][3]));
        *reinterpret_cast<float4*>(&g_po[slot][r0 + i][c0]) = v;
    }
    if (tc == 0) {
#pragma unroll
        for (int i = 0; i < 4; i++) {
            g_pm[slot][r0 + i] = m[i];
            g_pl[slot][r0 + i] = l[i];
        }
    }
}

// ----------------------------------------------------------------------------
// Kernel 3: combine split-KV partials. Grid (NQT, B), 256 threads.
// ----------------------------------------------------------------------------
__global__ __launch_bounds__(256) void combine_kernel(float* __restrict__ out) {
    const int t  = threadIdx.x;
    const int tr = t >> 4;
    const int tc = t & 15;
    const int qb = blockIdx.x;
    const int b  = blockIdx.y;

    const int nch   = (qb + CHUNK) / CHUNK;   // ceil((qb+1)/CHUNK)
    const int slot0 = ((b * NQT) + qb) * MAXCH;

#pragma unroll
    for (int i = 0; i < 4; i++) {
        const int row = tr * 4 + i;

        float M = -1e30f;
        for (int c = 0; c < nch; c++) M = fmaxf(M, g_pm[slot0 + c][row]);
        float L = 0.f;
        float w[MAXCH];
        for (int c = 0; c < nch; c++) {
            w[c] = __expf(g_pm[slot0 + c][row] - M);
            L += g_pl[slot0 + c][row] * w[c];
        }
        const float invL = 1.0f / L;

        float acc[4] = {0.f, 0.f, 0.f, 0.f};
        for (int c = 0; c < nch; c++) {
            const float4 v = *reinterpret_cast<const float4*>(&g_po[slot0 + c][row][tc * 4]);
            acc[0] = fmaf(v.x, w[c], acc[0]);
            acc[1] = fmaf(v.y, w[c], acc[1]);
            acc[2] = fmaf(v.z, w[c], acc[2]);
            acc[3] = fmaf(v.w, w[c], acc[3]);
        }

        const size_t orow = (size_t)b * LL + qb * 64 + row;
        float4 r = make_float4(acc[0] * invL, acc[1] * invL, acc[2] * invL, acc[3] * invL);
        *reinterpret_cast<float4*>(&out[orow * HH + tc * 4]) = r;
    }
}

// ----------------------------------------------------------------------------
extern "C" void kernel_launch(void* const* d_in, const int* in_sizes, int n_in,
                              void* d_out, int out_size) {
    const float* x  = (const float*)d_in[0];   // [B, L, D] fp32
    const float* Wq = (const float*)d_in[1];   // [H, D]    fp32
    float* out = (float*)d_out;                // [B, L, H] fp32

    proj_kernel<<<(BB * LL) / 64, 256>>>(x, Wq);
    attn_split_kernel<<<dim3(NBLK, BB), 256>>>();
    combine_kernel<<<dim3(NQT, BB), 256>>>(out);
}

// round 15
// speedup vs baseline: 1.0309x; 1.0309x over previous
#include <cuda_runtime.h>

// Shapes (fixed by problem)
#define BB 4
#define LL 2048
#define DD 1024
#define HH 64

#define NQT 32          // q tiles per batch (L/64)
#define CHUNK 8         // key tiles per split-KV chunk
#define MAXCH 4         // max chunks per q tile
#define NBLK 80         // chunk-blocks per batch: 8*1 + 8*2 + 8*3 + 8*4

#define KSPLIT 4        // proj split-K factor
#define KRANGE (DD / KSPLIT)   // 256

// Scratch (device globals -- no allocation allowed)
__device__ float g_q[BB * LL * HH];                         // 2 MB
__device__ float g_qp[KSPLIT * BB * LL * HH];               // 8 MB proj partials
__device__ float g_po[BB * NQT * MAXCH][64][HH];            // 8 MB partial O (unnormalized)
__device__ float g_pm[BB * NQT * MAXCH][64];                // partial row max
__device__ float g_pl[BB * NQT * MAXCH][64];                // partial row sum

// ---------------- packed fp32x2 helpers (FFMA2 path, sm_103a) ----------------
typedef unsigned long long u64;

__device__ __forceinline__ void ffma2(u64& d, u64 a, u64 b) {
    asm("fma.rn.f32x2 %0, %1, %2, %0;" : "+l"(d) : "l"(a), "l"(b));
}
__device__ __forceinline__ void mul2(u64& d, u64 a, u64 b) {
    asm("mul.rn.f32x2 %0, %1, %2;" : "=l"(d) : "l"(a), "l"(b));
}
__device__ __forceinline__ u64 pack2(float lo, float hi) {
    u64 r;
    asm("mov.b64 %0, {%1, %2};" : "=l"(r) : "f"(lo), "f"(hi));
    return r;
}
__device__ __forceinline__ float2 unpack2(u64 v) {
    float2 r;
    asm("mov.b64 {%0, %1}, %2;" : "=f"(r.x), "=f"(r.y) : "l"(v));
    return r;
}
__device__ __forceinline__ float hsum2(u64 v) {
    float2 u = unpack2(v);
    return u.x + u.y;
}

// ----------------------------------------------------------------------------
// Kernel 1: q = x @ Wq^T  (M=8192, N=64, K=1024), dot2 FFMA2 core, SPLIT-K x4.
// Grid (128, 4): blockIdx.y selects K range [ks*256, ks*256+256).
// Partials to g_qp; qreduce_kernel sums the 4 splits.
// ----------------------------------------------------------------------------
__global__ __launch_bounds__(256) void proj_kernel(const float* __restrict__ x,
                                                   const float* __restrict__ Wq) {
    __shared__ float xs[64][64];      // [m][k] plain, 16 KB
    __shared__ u64   smW[64 * 32];    // [n][kpair ^ swz(n)], 16 KB

    const int t  = threadIdx.x;
    const int tr = t >> 4;            // 0..15
    const int tc = t & 15;            // 0..15
    const int m0 = blockIdx.x * 64;
    const int ks = blockIdx.y;
    const int r0 = tr * 4;
    const int c0 = tc * 4;

    u64 acc2[4][4];                   // lanes = (even-k partial, odd-k partial)
#pragma unroll
    for (int i = 0; i < 4; i++)
#pragma unroll
        for (int j = 0; j < 4; j++) acc2[i][j] = 0ULL;

    const int kbeg = ks * KRANGE;
    for (int k0 = kbeg; k0 < kbeg + KRANGE; k0 += 64) {
#pragma unroll
        for (int i = 0; i < 4; i++) {
            int li4 = t + i * 256;          // 0..1023
            int r  = li4 >> 4;              // 0..63
            int c4 = (li4 & 15) * 4;        // 0..60
            // x tile: plain float4 store
            float4 vx = *reinterpret_cast<const float4*>(&x[(size_t)(m0 + r) * DD + k0 + c4]);
            *reinterpret_cast<float4*>(&xs[r][c4]) = vx;
            // Wq tile: pack k-pairs, swizzled u64 store
            float4 vw = *reinterpret_cast<const float4*>(&Wq[(size_t)r * DD + k0 + c4]);
            int sw = (r >> 2) & 15;
            smW[r * 32 + (((c4 >> 1) + 0) ^ sw)] = pack2(vw.x, vw.y);
            smW[r * 32 + (((c4 >> 1) + 1) ^ sw)] = pack2(vw.z, vw.w);
        }
        __syncthreads();

#pragma unroll 8
        for (int tt = 0; tt < 32; tt++) {
            u64 a2[4], b2[4];
#pragma unroll
            for (int i = 0; i < 4; i++)
                a2[i] = *reinterpret_cast<const u64*>(&xs[r0 + i][2 * tt]);
#pragma unroll
            for (int j = 0; j < 4; j++)
                b2[j] = smW[(c0 + j) * 32 + (tt ^ tc)];
#pragma unroll
            for (int i = 0; i < 4; i++)
#pragma unroll
                for (int j = 0; j < 4; j++) ffma2(acc2[i][j], a2[i], b2[j]);
        }
        __syncthreads();
    }

    float* qp = g_qp + (size_t)ks * (BB * LL * HH);
#pragma unroll
    for (int i = 0; i < 4; i++) {
        float4 v = make_float4(hsum2(acc2[i][0]), hsum2(acc2[i][1]),
                               hsum2(acc2[i][2]), hsum2(acc2[i][3]));
        *reinterpret_cast<float4*>(&qp[(size_t)(m0 + r0 + i) * HH + c0]) = v;
    }
}

// ----------------------------------------------------------------------------
// Kernel 1b: sum the 4 K-split partials into g_q. 512 blocks x 256 thr x float4.
// ----------------------------------------------------------------------------
__global__ __launch_bounds__(256) void qreduce_kernel() {
    const int idx4 = (blockIdx.x * 256 + threadIdx.x) * 4;   // float index, x4
    const size_t N = (size_t)BB * LL * HH;
    float4 a = *reinterpret_cast<const float4*>(&g_qp[idx4]);
#pragma unroll
    for (int s = 1; s < KSPLIT; s++) {
        float4 b = *reinterpret_cast<const float4*>(&g_qp[s * N + idx4]);
        a.x += b.x; a.y += b.y; a.z += b.z; a.w += b.w;
    }
    *reinterpret_cast<float4*>(&g_q[idx4]) = a;
}

// ----------------------------------------------------------------------------
// Kernel 2: split-KV causal flash attention, dot2 FFMA2 core, reg-prefetched
// K-tile pipeline. Smem (48 KB exactly):
//   qs  [64][64] plain         -- Q, a-side of S (broadcast reads)
//   smA [64*32] u64            -- K d-pairs swizzled (b-side of S); ALIASED by
//                                 P kk-pairs after S phase (sync-separated)
//   smB [64*32] u64 (floats)   -- K transposed [d][key] swizzled (b-side of PV)
// ----------------------------------------------------------------------------
__global__ __launch_bounds__(256, 2) void attn_split_kernel() {
    __shared__ float qs[64][64];
    __shared__ u64   smA[64 * 32];
    __shared__ u64   smB[64 * 32];

    float* Bf = reinterpret_cast<float*>(smB);

    const int t  = threadIdx.x;
    const int tr = t >> 4;
    const int tc = t & 15;
    const int b  = blockIdx.y;
    const int r0 = tr * 4;
    const int c0 = tc * 4;

    // map flat chunk id -> (qb, ci)
    int id = blockIdx.x;              // 0..79
    int qb, ci;
    if (id < 8)       { qb = id;                 ci = 0; }
    else if (id < 24) { int e = id - 8;  qb = 8  + (e >> 1); ci = e & 1; }
    else if (id < 48) { int e = id - 24; qb = 16 + e / 3;    ci = e % 3; }
    else              { int e = id - 48; qb = 24 + (e >> 2); ci = e & 3; }

    const int jstart = ci * CHUNK;
    const int jend   = min(jstart + CHUNK, qb + 1);   // exclusive

    const float* qbase = g_q + (size_t)b * LL * HH;

    // Load q tile [64 x 64] plain
#pragma unroll
    for (int i = 0; i < 4; i++) {
        int li4 = t + i * 256;
        int r  = li4 >> 4;
        int c4 = (li4 & 15) * 4;
        float4 v = *reinterpret_cast<const float4*>(&qbase[(size_t)(qb * 64 + r) * HH + c4]);
        *reinterpret_cast<float4*>(&qs[r][c4]) = v;
    }

    // Prefetch first K tile into registers (gmem -> regs, no smem involved)
    float4 pf[4];
#pragma unroll
    for (int i = 0; i < 4; i++) {
        int li4 = t + i * 256;
        int r  = li4 >> 4;
        int c4 = (li4 & 15) * 4;
        pf[i] = *reinterpret_cast<const float4*>(&qbase[(size_t)(jstart * 64 + r) * HH + c4]);
    }

    float m[4], l[4];
    u64 o2[4][4];                     // lanes = (even-kk partial, odd-kk partial)
#pragma unroll
    for (int i = 0; i < 4; i++) { m[i] = -1e30f; l[i] = 0.f; }
#pragma unroll
    for (int i = 0; i < 4; i++)
#pragma unroll
        for (int j = 0; j < 4; j++) o2[i][j] = 0ULL;

    for (int j0 = jstart; j0 < jend; j0++) {
        __syncthreads();   // prior PV reads of smA/smB done; qs writes visible
        // Store prefetched k tile: A = [key][d-pair ^ swz] u64;
        //                          B = transpose [d][key ^ 2*swz] floats
#pragma unroll
        for (int i = 0; i < 4; i++) {
            int li4 = t + i * 256;
            int r  = li4 >> 4;              // key
            int c4 = (li4 & 15) * 4;        // d
            float4 v = pf[i];
            int swA = (r >> 2) & 15;
            smA[r * 32 + (((c4 >> 1) + 0) ^ swA)] = pack2(v.x, v.y);
            smA[r * 32 + (((c4 >> 1) + 1) ^ swA)] = pack2(v.z, v.w);
            Bf[(c4 + 0) * 64 + (r ^ ((((c4 + 0) >> 2) & 15) << 1))] = v.x;
            Bf[(c4 + 1) * 64 + (r ^ ((((c4 + 1) >> 2) & 15) << 1))] = v.y;
            Bf[(c4 + 2) * 64 + (r ^ ((((c4 + 2) >> 2) & 15) << 1))] = v.z;
            Bf[(c4 + 3) * 64 + (r ^ ((((c4 + 3) >> 2) & 15) << 1))] = v.w;
        }
        // Issue prefetch for NEXT tile now; LDG latency overlaps S+softmax+PV
        if (j0 + 1 < jend) {
#pragma unroll
            for (int i = 0; i < 4; i++) {
                int li4 = t + i * 256;
                int r  = li4 >> 4;
                int c4 = (li4 & 15) * 4;
                pf[i] = *reinterpret_cast<const float4*>(
                    &qbase[(size_t)((j0 + 1) * 64 + r) * HH + c4]);
            }
        }
        __syncthreads();

        // ---- S = (Q K^T) / 32, dot2 over d ----
        u64 s2[4][4];
#pragma unroll
        for (int i = 0; i < 4; i++)
#pragma unroll
            for (int j = 0; j < 4; j++) s2[i][j] = 0ULL;

#pragma unroll 8
        for (int tt = 0; tt < 32; tt++) {
            u64 a2[4], b2[4];
#pragma unroll
            for (int i = 0; i < 4; i++)
                a2[i] = *reinterpret_cast<const u64*>(&qs[r0 + i][2 * tt]);
#pragma unroll
            for (int j = 0; j < 4; j++)
                b2[j] = smA[(c0 + j) * 32 + (tt ^ tc)];
#pragma unroll
            for (int i = 0; i < 4; i++)
#pragma unroll
                for (int j = 0; j < 4; j++) ffma2(s2[i][j], a2[i], b2[j]);
        }

        float s[4][4];
#pragma unroll
        for (int i = 0; i < 4; i++)
#pragma unroll
            for (int j = 0; j < 4; j++)
                s[i][j] = hsum2(s2[i][j]) * 0.03125f;   // 1/sqrt(1024)

        if (j0 == qb) {
#pragma unroll
            for (int i = 0; i < 4; i++)
#pragma unroll
                for (int j = 0; j < 4; j++)
                    if (c0 + j > r0 + i) s[i][j] = -1e30f;
        }

        // ---- online softmax (row reduced across 16 tc lanes) ----
        float alpha[4];
#pragma unroll
        for (int i = 0; i < 4; i++) {
            float mx = fmaxf(fmaxf(s[i][0], s[i][1]), fmaxf(s[i][2], s[i][3]));
#pragma unroll
            for (int off = 8; off >= 1; off >>= 1)
                mx = fmaxf(mx, __shfl_xor_sync(0xffffffffu, mx, off));
            float mn = fmaxf(m[i], mx);
            alpha[i] = __expf(m[i] - mn);
            m[i] = mn;
            float rs = 0.f;
#pragma unroll
            for (int j = 0; j < 4; j++) {
                s[i][j] = __expf(s[i][j] - mn);
                rs += s[i][j];
            }
#pragma unroll
            for (int off = 8; off >= 1; off >>= 1)
                rs += __shfl_xor_sync(0xffffffffu, rs, off);
            l[i] = l[i] * alpha[i] + rs;
        }
        // rescale packed O accumulators (both lanes are partials of same output)
#pragma unroll
        for (int i = 0; i < 4; i++) {
            u64 ap = pack2(alpha[i], alpha[i]);
#pragma unroll
            for (int j = 0; j < 4; j++) mul2(o2[i][j], o2[i][j], ap);
        }

        __syncthreads();   // all S reads of smA done before aliasing with P
        // ---- write P as kk-pairs into smA (alias) ----
#pragma unroll
        for (int i = 0; i < 4; i++) {
            smA[(r0 + i) * 32 + 2 * tc + 0] = pack2(s[i][0], s[i][1]);
            smA[(r0 + i) * 32 + 2 * tc + 1] = pack2(s[i][2], s[i][3]);
        }
        __syncthreads();

        // ---- O += P @ V (V = K tile), dot2 over kk ----
#pragma unroll 8
        for (int tt = 0; tt < 32; tt++) {
            u64 a2[4], b2[4];
#pragma unroll
            for (int i = 0; i < 4; i++)
                a2[i] = smA[(r0 + i) * 32 + tt];
#pragma unroll
            for (int j = 0; j < 4; j++)
                b2[j] = smB[(c0 + j) * 32 + (tt ^ tc)];
#pragma unroll
            for (int i = 0; i < 4; i++)
#pragma unroll
                for (int j = 0; j < 4; j++) ffma2(o2[i][j], a2[i], b2[j]);
        }
    }

    // Epilogue: reduce pairs, store unnormalized partials + (m, l)
    const int slot = ((b * NQT) + qb) * MAXCH + ci;
#pragma unroll
    for (int i = 0; i < 4; i++) {
        float4 v = make_float4(hsum2(o2[i][0]), hsum2(o2[i][1]),
                               hsum2(o2[i][2]), hsum2(o2[i][3]));
        *reinterpret_cast<float4*>(&g_po[slot][r0 + i][c0]) = v;
    }
    if (tc == 0) {
#pragma unroll
        for (int i = 0; i < 4; i++) {
            g_pm[slot][r0 + i] = m[i];
            g_pl[slot][r0 + i] = l[i];
        }
    }
}

// ----------------------------------------------------------------------------
// Kernel 3: combine split-KV partials. Grid (NQT, B), 256 threads.
// ----------------------------------------------------------------------------
__global__ __launch_bounds__(256) void combine_kernel(float* __restrict__ out) {
    const int t  = threadIdx.x;
    const int tr = t >> 4;
    const int tc = t & 15;
    const int qb = blockIdx.x;
    const int b  = blockIdx.y;

    const int nch   = (qb + CHUNK) / CHUNK;   // ceil((qb+1)/CHUNK)
    const int slot0 = ((b * NQT) + qb) * MAXCH;

#pragma unroll
    for (int i = 0; i < 4; i++) {
        const int row = tr * 4 + i;

        float M = -1e30f;
        for (int c = 0; c < nch; c++) M = fmaxf(M, g_pm[slot0 + c][row]);
        float L = 0.f;
        float w[MAXCH];
        for (int c = 0; c < nch; c++) {
            w[c] = __expf(g_pm[slot0 + c][row] - M);
            L += g_pl[slot0 + c][row] * w[c];
        }
        const float invL = 1.0f / L;

        float acc[4] = {0.f, 0.f, 0.f, 0.f};
        for (int c = 0; c < nch; c++) {
            const float4 v = *reinterpret_cast<const float4*>(&g_po[slot0 + c][row][tc * 4]);
            acc[0] = fmaf(v.x, w[c], acc[0]);
            acc[1] = fmaf(v.y, w[c], acc[1]);
            acc[2] = fmaf(v.z, w[c], acc[2]);
            acc[3] = fmaf(v.w, w[c], acc[3]);
        }

        const size_t orow = (size_t)b * LL + qb * 64 + row;
        float4 r = make_float4(acc[0] * invL, acc[1] * invL, acc[2] * invL, acc[3] * invL);
        *reinterpret_cast<float4*>(&out[orow * HH + tc * 4]) = r;
    }
}

// ----------------------------------------------------------------------------
extern "C" void kernel_launch(void* const* d_in, const int* in_sizes, int n_in,
                              void* d_out, int out_size) {
    const float* x  = (const float*)d_in[0];   // [B, L, D] fp32
    const float* Wq = (const float*)d_in[1];   // [H, D]    fp32
    float* out = (float*)d_out;                // [B, L, H] fp32

    proj_kernel<<<dim3((BB * LL) / 64, KSPLIT), 256>>>(x, Wq);
    qreduce_kernel<<<(BB * LL * HH) / (256 * 4), 256>>>();
    attn_split_kernel<<<dim3(NBLK, BB), 256>>>();
    combine_kernel<<<dim3(NQT, BB), 256>>>(out);
}